// round 10
// baseline (speedup 1.0000x reference)
#include <cuda_runtime.h>

#define NB 16
#define NH 16
#define NI 512
#define NE 512
#define IE (NI * NE)
#define JSPLIT 4

// emb partials (device scratch; allocations forbidden)
__device__ float g_embp[JSPLIT][NB * NH * NE];  // 2 MB

// ---- packed fp32x2 helpers (FFMA2: ptxas never emits it from C++) ----------
__device__ __forceinline__ unsigned long long pack2(float lo, float hi) {
    unsigned long long r;
    asm("mov.b64 %0, {%1, %2};" : "=l"(r) : "f"(lo), "f"(hi));
    return r;
}
__device__ __forceinline__ void fma2(unsigned long long& d,
                                     unsigned long long a, unsigned long long b) {
    asm("fma.rn.f32x2 %0, %1, %2, %0;" : "+l"(d) : "l"(a), "l"(b));
}
__device__ __forceinline__ float2 unpack2(unsigned long long v) {
    float2 r;
    asm("mov.b64 {%0, %1}, %2;" : "=f"(r.x), "=f"(r.y) : "l"(v));
    return r;
}

// ---------------------------------------------------------------------------
// Kernel 1: emb partials. g_embp[js][b,h,e] = sum_{j in 128-slice} x*Wv
// Tile widened to 8b x 16h (128 acc regs, 1 block/SM): L2 traffic 64->48 MB
// -- the measured warm bottleneck. Block = 8b x 16h x 32e x 128j; 256 thr =
// 32 e-lanes x 8 j-slices; per j: 24 broadcast LDG.32 + 128 FMA.
// Grid 128 = 16ec x 2bg x 4js -> single wave at 1 block/SM.
// Also bias-inits the output (4 elements/thread).
// ---------------------------------------------------------------------------
__global__ __launch_bounds__(256, 1) void emb_kernel(const float* __restrict__ x,
                                                     const float* __restrict__ wv,
                                                     const float* __restrict__ bias,
                                                     float* __restrict__ out) {
    const int t   = threadIdx.x;
    const int bid = blockIdx.x;        // 128 blocks

    // Bias init of the output (gemm accumulates on top). 128*256*4 = 131072.
    {
        const int oidx = bid * 256 + t;            // 0 .. 32767
        const float bv = bias[oidx & (NE - 1)];    // 32768 % 512 == 0
#pragma unroll
        for (int p = 0; p < 4; ++p) out[oidx + p * 32768] = bv;
    }

    const int el  = t & 31;            // e lane (coalesced)
    const int sl  = t >> 5;            // j slice (warp id) 0..7
    const int ec  = bid & 15;          // e chunk 0..15
    const int bg  = (bid >> 4) & 1;    // b half
    const int js  = bid >> 5;          // j split 0..3

    const int e = ec * 32 + el;
    const float* xp = x  + bg * 8 * IE + e;
    const float* wp = wv + e;          // all 16 heads

    float acc[8][16];
#pragma unroll
    for (int i = 0; i < 8; ++i)
#pragma unroll
        for (int k = 0; k < 16; ++k) acc[i][k] = 0.f;

    const int j0 = js * 128;
    for (int jj = 0; jj < 16; ++jj) {
        const int joff = (j0 + sl + jj * 8) * NE;
        float xv[8], wv16[16];
#pragma unroll
        for (int i = 0; i < 8; ++i)  xv[i]   = __ldg(xp + i * IE + joff);
#pragma unroll
        for (int k = 0; k < 16; ++k) wv16[k] = __ldg(wp + k * IE + joff);
#pragma unroll
        for (int i = 0; i < 8; ++i)
#pragma unroll
            for (int k = 0; k < 16; ++k)
                acc[i][k] = fmaf(xv[i], wv16[k], acc[i][k]);
    }

    // Reduce the 8 j-slices: 4 chunks of 32 (b,h) pairs through 32KB smem.
    __shared__ float red[8][32][32];   // [slice][ik][el] - conflict-free both ways
    const int b0 = bg * 8;
#pragma unroll
    for (int c = 0; c < 4; ++c) {
        __syncthreads();
#pragma unroll
        for (int ik = 0; ik < 32; ++ik) {
            const int ikf = c * 32 + ik;           // b_i*16 + h
            red[sl][ik][el] = acc[ikf >> 4][ikf & 15];
        }
        __syncthreads();
#pragma unroll
        for (int r = 0; r < 4; ++r) {
            const int ik = r * 8 + sl;
            float s = 0.f;
#pragma unroll
            for (int q = 0; q < 8; ++q) s += red[q][ik][el];
            const int ikf = c * 32 + ik;
            const int b = b0 + (ikf >> 4);
            const int h = ikf & 15;
            g_embp[js][(b * NH + h) * NE + e] = s;
        }
    }
}

// ---------------------------------------------------------------------------
// Kernel 2: out[m][n] += sum_k emb[m][k]*w[n][k]  (bias already in out)
// R8 structure (grid 128, 64x64 tiles, split-K=4 as two 64-k smem stages,
// JSPLIT=4 A-fold, REDG epilogue) with the inner product re-packed as
// FFMA2 (fma.rn.f32x2): 8 packed FMA + 6 movs per kk vs 16 FFMA ->
// FMA-pipe cycles halved (the gemm floor at measured clocks).
// ---------------------------------------------------------------------------
__global__ __launch_bounds__(256) void gemm_kernel(const float* __restrict__ w,
                                                   float* __restrict__ out) {
    const int t   = threadIdx.x;
    const int bid = blockIdx.x;        // 128 = 4 mt x 8 nt x 4 kt
    const int kt  = bid & 3;
    const int nt  = (bid >> 2) & 7;
    const int mt  = bid >> 5;
    const int m0 = mt * 64, n0 = nt * 64;

    __shared__ __align__(16) float sa[64][68];  // [k][m]
    __shared__ __align__(16) float sb[64][68];  // [k][n]

    const int tx = t & 15;   // n micro-tile
    const int ty = t >> 4;   // m micro-tile
    unsigned long long acc2[4][2];
#pragma unroll
    for (int i = 0; i < 4; ++i) {
        acc2[i][0] = pack2(0.f, 0.f);
        acc2[i][1] = pack2(0.f, 0.f);
    }

#pragma unroll
    for (int kc = 0; kc < 2; ++kc) {
        const int k0 = kt * 128 + kc * 64;
        if (kc) __syncthreads();   // previous chunk's compute done before reload

#pragma unroll
        for (int r = 0; r < 4; ++r) {
            const int lin = t + r * 256;        // 0..1023 float4 slots
            const int row = lin >> 4;           // 0..63
            const int kq  = (lin & 15) * 4;     // 0..60
            const int aoff = (m0 + row) * NE + k0 + kq;
            float4 a = *(const float4*)&g_embp[0][aoff];
#pragma unroll
            for (int p = 1; p < JSPLIT; ++p) {
                const float4 v = *(const float4*)&g_embp[p][aoff];
                a.x += v.x; a.y += v.y; a.z += v.z; a.w += v.w;
            }
            sa[kq + 0][row] = a.x;
            sa[kq + 1][row] = a.y;
            sa[kq + 2][row] = a.z;
            sa[kq + 3][row] = a.w;
            const float4 b4 = *(const float4*)&w[(n0 + row) * NE + k0 + kq];
            sb[kq + 0][row] = b4.x;
            sb[kq + 1][row] = b4.y;
            sb[kq + 2][row] = b4.z;
            sb[kq + 3][row] = b4.w;
        }
        __syncthreads();

#pragma unroll 8
        for (int kk = 0; kk < 64; ++kk) {
            const float4 av = *(const float4*)&sa[kk][ty * 4];
            const float4 bv = *(const float4*)&sb[kk][tx * 4];
            const unsigned long long b01 = pack2(bv.x, bv.y);
            const unsigned long long b23 = pack2(bv.z, bv.w);
            const float a4[4] = {av.x, av.y, av.z, av.w};
#pragma unroll
            for (int i = 0; i < 4; ++i) {
                const unsigned long long ai = pack2(a4[i], a4[i]);
                fma2(acc2[i][0], ai, b01);
                fma2(acc2[i][1], ai, b23);
            }
        }
    }

    // Split-K accumulate directly into the bias-initialized output.
#pragma unroll
    for (int i = 0; i < 4; ++i) {
        float* op = &out[(m0 + ty * 4 + i) * NE + n0 + tx * 4];
        const float2 v01 = unpack2(acc2[i][0]);
        const float2 v23 = unpack2(acc2[i][1]);
        atomicAdd(op + 0, v01.x);
        atomicAdd(op + 1, v01.y);
        atomicAdd(op + 2, v23.x);
        atomicAdd(op + 3, v23.y);
    }
}

extern "C" void kernel_launch(void* const* d_in, const int* in_sizes, int n_in,
                              void* d_out, int out_size) {
    const float* x    = (const float*)d_in[0];  // [16,1,512,512]
    // d_in[1] = W_q, d_in[2] = W_k: mathematically dead (softmax cols sum to 1)
    const float* wv   = (const float*)d_in[3];  // [1,16,512,512]
    const float* mlpw = (const float*)d_in[4];  // [512,512]
    const float* mlpb = (const float*)d_in[5];  // [512]
    float* out = (float*)d_out;                 // [16,16,512]

    emb_kernel<<<128, 256>>>(x, wv, mlpb, out);
    gemm_kernel<<<128, 256>>>(mlpw, out);
}